// round 14
// baseline (speedup 1.0000x reference)
#include <cuda_runtime.h>
#include <cuda_fp16.h>
#include <cstdint>

#define BN 2048   // B*N rows
#define NN 256    // N (neighbors)
#define D  128
#define E  64

// Scratch (device globals: allocation-free rule)
__device__ __align__(16) float g_aggmean[BN * D];
__device__ __align__(16) float g_aggmax[BN * D];

__device__ __forceinline__ float tanh_fast(float x) {
    float y;
    asm("tanh.approx.f32 %0, %1;" : "=f"(y) : "f"(x));
    return y;
}

__device__ __forceinline__ uint32_t pack_h2(float a, float b) {
    __half2 v = __floats2half2_rn(a, b);   // a = low half (even k)
    uint32_t r;
    memcpy(&r, &v, 4);
    return r;
}

// ---------------------------------------------------------------------------
// K2: 4 (b,i) rows per CTA (grid 512).
//  - W2 B-fragments (0.5*W2, fp16-packed) loaded ONCE per CTA directly from
//    global into 32 registers: no sW2T SMEM buffer, no per-tile fragment LDS.
//  - hW1 prologue overlapped with staging (h via __ldg, W1 direct).
//  - ef loads software-pipelined: tile t+1's edge feats prefetched during
//    tile t's MMA + epilogue.
//  - Accumulators init 0.5*b2 -> MMA yields 0.5*logit; tanh-space reduction:
//    S = sum(vm*th), T = max(sgn_d*th); final mean/max recovered per d.
// SMEM ~17KB.
// ---------------------------------------------------------------------------
#define K2_SMEM_BYTES (4168 * 4)

__global__ void __launch_bounds__(256) k2_main(
    const float* __restrict__ h, const float* __restrict__ ef,
    const unsigned char* __restrict__ adj,
    const float* __restrict__ W1, const float* __restrict__ b1,
    const float* __restrict__ W2, const float* __restrict__ b2) {
    extern __shared__ float sm[];
    uint32_t* sRh   = (uint32_t*)sm;          // [row][epair] packed half2, pitch 36 (2304)
    float* s_hW1x = sm + 2304;   // [4][64]
    float* sW1e   = sm + 2560;   // [3][64]
    float* s_b2   = sm + 2752;   // [128] = 0.5*b2
    float* s_hx   = sm + 2880;   // [4][128]
    float* s_redS = sm + 3392;   // [2][128]
    float* s_redT = sm + 3648;   // [2][128]
    int*   s_jidx = (int*)(sm + 3904);  // 256
    int*   s_misc = (int*)(sm + 4160);  // 8

    const int bi0  = blockIdx.x * 4;
    const int tid  = threadIdx.x;
    const int lane = tid & 31;
    const int warp = tid >> 5;
    const int gid  = lane >> 2;   // 0..7
    const int tg   = lane & 3;    // 0..3
    const int wm   = warp & 1;    // M-group (rows)
    const int wn   = warp >> 1;   // N-group (cols)

    if (tid < 128) {
        const int r = tid >> 5, c = tid & 31;
        ((float4*)&s_hx[r * 128])[c] = ((const float4*)(h + (size_t)(bi0 + r) * D))[c];
    }
    for (int idx = tid; idx < 3 * E; idx += 256) sW1e[idx] = W1[D * E + idx];
    if (tid < D) s_b2[tid] = 0.5f * b2[tid];

    // ---- W2 B-fragments: once per CTA, straight to registers ----
    uint32_t bfr[4][4][2];
#pragma unroll
    for (int kc = 0; kc < 4; kc++)
#pragma unroll
        for (int nt = 0; nt < 4; nt++) {
            const int col = wn * 32 + nt * 8 + gid;
            const int ep0 = kc * 8 + tg;
            bfr[kc][nt][0] = pack_h2(0.5f * __ldg(W2 + (2 * ep0) * D + col),
                                     0.5f * __ldg(W2 + (2 * ep0 + 1) * D + col));
            const int ep1 = ep0 + 4;
            bfr[kc][nt][1] = pack_h2(0.5f * __ldg(W2 + (2 * ep1) * D + col),
                                     0.5f * __ldg(W2 + (2 * ep1 + 1) * D + col));
        }

    // hW1 prologue (h via __ldg: overlaps the fragment/staging loads)
    {
        const int r = tid >> 6;
        const int e = tid & 63;
        const float* hr = h + (size_t)(bi0 + r) * D;
        float a0 = 0.f, a1 = 0.f;
#pragma unroll 8
        for (int k = 0; k < 128; k += 2) {
            a0 = fmaf(__ldg(hr + k),     W1[k * E + e],       a0);
            a1 = fmaf(__ldg(hr + k + 1), W1[(k + 1) * E + e], a1);
        }
        s_hW1x[r * 64 + e] = a0 + a1 + b1[e];
    }

    for (int sub = 0; sub < 4; sub++) {
        const int bi = bi0 + sub;
        __syncthreads();   // staging/prologue complete (sub 0); buffer reuse (sub>0)

        const float* s_hW1 = s_hW1x + sub * 64;
        const float* s_h   = s_hx + sub * 128;

        const bool m = adj[(size_t)bi * NN + tid] != 0;
        const unsigned bal = __ballot_sync(0xffffffffu, m);
        if (lane == 0) s_misc[warp] = __popc(bal);
        __syncthreads();
        int base = 0, cnt = 0;
#pragma unroll
        for (int w = 0; w < 8; w++) {
            const int c = s_misc[w];
            if (w < warp) base += c;
            cnt += c;
        }
        if (m) s_jidx[base + __popc(bal & ((1u << lane) - 1u))] = tid;
        __syncthreads();

        // Per-sub per-thread constants: half-bias + sign for the 8 d's
        float bh[8], sgn[8];
#pragma unroll
        for (int nt = 0; nt < 4; nt++)
#pragma unroll
            for (int q = 0; q < 2; q++) {
                const int d = wn * 32 + nt * 8 + 2 * tg + q;
                bh[nt * 2 + q]  = s_b2[d];
                sgn[nt * 2 + q] = (s_h[d] >= 0.f) ? 1.f : -1.f;
            }

        float S[8], T[8];
#pragma unroll
        for (int i = 0; i < 8; i++) { S[i] = 0.f; T[i] = -1e30f; }

        const int nTiles = (cnt + 63) >> 6;
        const int rrow = tid >> 2;
        const int re0  = (tid & 3) << 4;
        const int rp0  = (tid & 3) << 3;

        // ---- Pipelined ef preload for tile 0 ----
        float f0 = 0.f, f1 = 0.f, f2v = 0.f;
        if (rrow < cnt) {
            const float* p = ef + ((size_t)bi * NN + s_jidx[rrow]) * 3;
            f0 = p[0]; f1 = p[1]; f2v = p[2];
        }

        for (int t = 0; t < nTiles; t++) {
            if (t) __syncthreads();  // protect sRh reuse across tiles
            // ---- Build R tile (64 rows x 64 e) from preloaded ef ----
#pragma unroll
            for (int i = 0; i < 8; i++) {
                const int e0 = re0 + 2 * i;
                float pa = s_hW1[e0]     + f0 * sW1e[e0]     + f1 * sW1e[64 + e0]     + f2v * sW1e[128 + e0];
                float pb = s_hW1[e0 + 1] + f0 * sW1e[e0 + 1] + f1 * sW1e[64 + e0 + 1] + f2v * sW1e[128 + e0 + 1];
                pa = fmaxf(pa, 0.f); pb = fmaxf(pb, 0.f);
                sRh[rrow * 36 + rp0 + i] = pack_h2(pa, pb);
            }
            __syncthreads();

            // ---- Prefetch next tile's ef (overlaps MMA + epilogue) ----
            f0 = 0.f; f1 = 0.f; f2v = 0.f;
            {
                const int jg = (t + 1) * 64 + rrow;
                if (jg < cnt) {
                    const float* p = ef + ((size_t)bi * NN + s_jidx[jg]) * 3;
                    f0 = p[0]; f1 = p[1]; f2v = p[2];
                }
            }

            // ---- 64x128 half-logits: init accum with 0.5*b2 ----
            float c[2][4][4];
#pragma unroll
            for (int mt = 0; mt < 2; mt++)
#pragma unroll
                for (int nt = 0; nt < 4; nt++)
#pragma unroll
                    for (int q = 0; q < 4; q++) c[mt][nt][q] = bh[nt * 2 + (q & 1)];

#pragma unroll
            for (int kc = 0; kc < 4; kc++) {
                const int kp = kc * 8;
                uint32_t a[2][4];
#pragma unroll
                for (int mt = 0; mt < 2; mt++) {
                    const int row = wm * 32 + mt * 16 + gid;
                    const uint32_t* pr = sRh + row * 36 + kp + tg;
                    a[mt][0] = pr[0];
                    a[mt][1] = pr[8 * 36];
                    a[mt][2] = pr[4];
                    a[mt][3] = pr[8 * 36 + 4];
                }
#pragma unroll
                for (int mt = 0; mt < 2; mt++)
#pragma unroll
                    for (int nt = 0; nt < 4; nt++) {
                        asm("mma.sync.aligned.m16n8k16.row.col.f32.f16.f16.f32 "
                            "{%0,%1,%2,%3}, {%4,%5,%6,%7}, {%8,%9}, {%0,%1,%2,%3};\n"
                            : "+f"(c[mt][nt][0]), "+f"(c[mt][nt][1]),
                              "+f"(c[mt][nt][2]), "+f"(c[mt][nt][3])
                            : "r"(a[mt][0]), "r"(a[mt][1]), "r"(a[mt][2]), "r"(a[mt][3]),
                              "r"(bfr[kc][nt][0]), "r"(bfr[kc][nt][1]));
                    }
            }

            // ---- Epilogue (tanh space): th = tanh(0.5*logit) ----
#pragma unroll
            for (int mt = 0; mt < 2; mt++)
#pragma unroll
                for (int q = 0; q < 4; q++) {
                    const int rloc = wm * 32 + mt * 16 + gid + ((q >> 1) << 3);
                    const float vm = ((t * 64 + rloc) < cnt) ? 1.f : 0.f;
#pragma unroll
                    for (int nt = 0; nt < 4; nt++) {
                        const int si = nt * 2 + (q & 1);
                        const float th = tanh_fast(c[mt][nt][q]);
                        S[si] = fmaf(vm, th, S[si]);
                        float tt = sgn[si] * th;
                        tt = (vm != 0.f) ? tt : -1e30f;
                        T[si] = fmaxf(T[si], tt);
                    }
                }
        }

        // ---- Reduce across the 8 lanes sharing each d ----
#pragma unroll
        for (int i = 0; i < 8; i++) {
#pragma unroll
            for (int off = 4; off < 32; off <<= 1) {
                S[i] += __shfl_xor_sync(0xffffffffu, S[i], off);
                T[i]  = fmaxf(T[i], __shfl_xor_sync(0xffffffffu, T[i], off));
            }
        }
        __syncthreads();
        if (lane < 4) {
#pragma unroll
            for (int nt = 0; nt < 4; nt++)
#pragma unroll
                for (int q = 0; q < 2; q++) {
                    const int d = wn * 32 + nt * 8 + 2 * lane + q;
                    const int si = nt * 2 + q;
                    s_redS[wm * 128 + d] = S[si];
                    s_redT[wm * 128 + d] = T[si];
                }
        }
        __syncthreads();
        if (tid < D) {
            const float St = s_redS[tid] + s_redS[128 + tid];
            const float Tt = fmaxf(s_redT[tid], s_redT[128 + tid]);
            const float hv = s_h[tid];
            const float cntf = (float)cnt;
            const float cl = (cnt > 0) ? cntf : 1.f;
            const float Sg = fmaf(0.5f, St, 0.5f * cntf);   // sum of sigmoids
            g_aggmean[(size_t)bi * D + tid] = Sg * hv / cl;
            float amax = 0.f;
            if (cnt > 0) {
                const float half_sgn = (hv >= 0.f) ? 0.5f : -0.5f;
                const float gstar = fmaf(half_sgn, Tt, 0.5f);
                amax = hv * gstar;
            }
            g_aggmax[(size_t)bi * D + tid] = amax;
        }
    }
}

// ---------------------------------------------------------------------------
// K3 (verbatim 23.4us proven config): upd MLP + residual + LayerNorm.
// TR=8 rows/CTA, 256 threads, grid=256, s_w tiles + reg prefetch + FFMA2.
// ---------------------------------------------------------------------------
#define TR 8
__global__ void __launch_bounds__(256) k3_upd(
    const float* __restrict__ h,
    const float* __restrict__ U1, const float* __restrict__ b3,
    const float* __restrict__ U2, const float* __restrict__ b4,
    const float* __restrict__ gamma, const float* __restrict__ beta,
    float* __restrict__ out) {
    __shared__ __align__(16) float s_inT[384][12];
    __shared__ __align__(16) float s_midT[128][12];
    __shared__ __align__(16) float s_w[32][128];
    __shared__ float s_x[TR][129];
    const int tid = threadIdx.x;
    const int r0 = blockIdx.x * TR;

    {
        const int r = tid >> 5, c = tid & 31;
        const int k = c * 4;
        const float4 va = ((const float4*)(h + (size_t)(r0 + r) * D))[c];
        const float4 vb = ((const float4*)(g_aggmean + (size_t)(r0 + r) * D))[c];
        const float4 vc = ((const float4*)(g_aggmax + (size_t)(r0 + r) * D))[c];
        s_inT[k + 0][r] = va.x; s_inT[k + 1][r] = va.y;
        s_inT[k + 2][r] = va.z; s_inT[k + 3][r] = va.w;
        s_inT[128 + k + 0][r] = vb.x; s_inT[128 + k + 1][r] = vb.y;
        s_inT[128 + k + 2][r] = vb.z; s_inT[128 + k + 3][r] = vb.w;
        s_inT[256 + k + 0][r] = vc.x; s_inT[256 + k + 1][r] = vc.y;
        s_inT[256 + k + 2][r] = vc.z; s_inT[256 + k + 3][r] = vc.w;
    }

    const int e  = tid & 127;
    const int rb = (tid >> 7) * 4;

    int lk[4], lc[4];
#pragma unroll
    for (int i = 0; i < 4; i++) { const int idx = tid + i * 256; lk[i] = idx >> 5; lc[i] = idx & 31; }

    unsigned long long a01 = 0ull, a23 = 0ull;
    float4 pf[4];
#pragma unroll
    for (int i = 0; i < 4; i++) pf[i] = ((const float4*)(U1 + lk[i] * D))[lc[i]];
    __syncthreads();

    for (int kc = 0; kc < 384; kc += 32) {
#pragma unroll
        for (int i = 0; i < 4; i++) *(float4*)&s_w[lk[i]][lc[i] * 4] = pf[i];
        __syncthreads();
        if (kc + 32 < 384) {
#pragma unroll
            for (int i = 0; i < 4; i++)
                pf[i] = ((const float4*)(U1 + (kc + 32 + lk[i]) * D))[lc[i]];
        }
#pragma unroll
        for (int kk = 0; kk < 32; kk++) {
            const float wv = s_w[kk][e];
            const ulonglong2 v = *(const ulonglong2*)&s_inT[kc + kk][rb];
            unsigned long long wp;
            asm("mov.b64 %0, {%1, %1};" : "=l"(wp) : "r"(__float_as_uint(wv)));
            asm("fma.rn.f32x2 %0, %1, %2, %0;" : "+l"(a01) : "l"(v.x), "l"(wp));
            asm("fma.rn.f32x2 %0, %1, %2, %0;" : "+l"(a23) : "l"(v.y), "l"(wp));
        }
        __syncthreads();
    }
    {
        const float bb = b3[e];
        uint32_t l0, h0, l1, h1;
        asm("mov.b64 {%0, %1}, %2;" : "=r"(l0), "=r"(h0) : "l"(a01));
        asm("mov.b64 {%0, %1}, %2;" : "=r"(l1), "=r"(h1) : "l"(a23));
        s_midT[e][rb + 0] = fmaxf(__uint_as_float(l0) + bb, 0.f);
        s_midT[e][rb + 1] = fmaxf(__uint_as_float(h0) + bb, 0.f);
        s_midT[e][rb + 2] = fmaxf(__uint_as_float(l1) + bb, 0.f);
        s_midT[e][rb + 3] = fmaxf(__uint_as_float(h1) + bb, 0.f);
    }
    a01 = 0ull; a23 = 0ull;
#pragma unroll
    for (int i = 0; i < 4; i++) pf[i] = ((const float4*)(U2 + lk[i] * D))[lc[i]];
    __syncthreads();

    for (int kc = 0; kc < 128; kc += 32) {
#pragma unroll
        for (int i = 0; i < 4; i++) *(float4*)&s_w[lk[i]][lc[i] * 4] = pf[i];
        __syncthreads();
        if (kc + 32 < 128) {
#pragma unroll
            for (int i = 0; i < 4; i++)
                pf[i] = ((const float4*)(U2 + (kc + 32 + lk[i]) * D))[lc[i]];
        }
#pragma unroll
        for (int kk = 0; kk < 32; kk++) {
            const float wv = s_w[kk][e];
            const ulonglong2 v = *(const ulonglong2*)&s_midT[kc + kk][rb];
            unsigned long long wp;
            asm("mov.b64 %0, {%1, %1};" : "=l"(wp) : "r"(__float_as_uint(wv)));
            asm("fma.rn.f32x2 %0, %1, %2, %0;" : "+l"(a01) : "l"(v.x), "l"(wp));
            asm("fma.rn.f32x2 %0, %1, %2, %0;" : "+l"(a23) : "l"(v.y), "l"(wp));
        }
        __syncthreads();
    }
    {
        const float b4v = b4[e];
        uint32_t l0, h0, l1, h1;
        asm("mov.b64 {%0, %1}, %2;" : "=r"(l0), "=r"(h0) : "l"(a01));
        asm("mov.b64 {%0, %1}, %2;" : "=r"(l1), "=r"(h1) : "l"(a23));
        s_x[rb + 0][e] = s_inT[e][rb + 0] + __uint_as_float(l0) + b4v;
        s_x[rb + 1][e] = s_inT[e][rb + 1] + __uint_as_float(h0) + b4v;
        s_x[rb + 2][e] = s_inT[e][rb + 2] + __uint_as_float(l1) + b4v;
        s_x[rb + 3][e] = s_inT[e][rb + 3] + __uint_as_float(h1) + b4v;
    }
    __syncthreads();

    const int warp = tid >> 5, lane = tid & 31;
    float s = 0.f, s2 = 0.f, v[4];
#pragma unroll
    for (int i = 0; i < 4; i++) {
        v[i] = s_x[warp][lane + i * 32];
        s += v[i]; s2 += v[i] * v[i];
    }
#pragma unroll
    for (int off = 1; off < 32; off <<= 1) {
        s  += __shfl_xor_sync(0xffffffffu, s, off);
        s2 += __shfl_xor_sync(0xffffffffu, s2, off);
    }
    const float mu  = s * (1.f / 128.f);
    const float var = s2 * (1.f / 128.f) - mu * mu;
    const float inv = rsqrtf(var + 1e-5f);
#pragma unroll
    for (int i = 0; i < 4; i++) {
        const int d = lane + i * 32;
        out[(size_t)(r0 + warp) * D + d] = (v[i] - mu) * inv * gamma[d] + beta[d];
    }
}

// ---------------------------------------------------------------------------
extern "C" void kernel_launch(void* const* d_in, const int* in_sizes, int n_in,
                              void* d_out, int out_size) {
    const float* h    = (const float*)d_in[0];
    const float* ef   = (const float*)d_in[1];
    const unsigned char* adj = (const unsigned char*)d_in[2];
    const float* W1   = (const float*)d_in[3];
    const float* b1   = (const float*)d_in[4];
    const float* W2   = (const float*)d_in[5];
    const float* b2   = (const float*)d_in[6];
    const float* U1   = (const float*)d_in[7];
    const float* b3   = (const float*)d_in[8];
    const float* U2   = (const float*)d_in[9];
    const float* b4   = (const float*)d_in[10];
    const float* gamma= (const float*)d_in[11];
    const float* beta = (const float*)d_in[12];
    float* out = (float*)d_out;

    cudaFuncSetAttribute(k2_main, cudaFuncAttributeMaxDynamicSharedMemorySize,
                         K2_SMEM_BYTES);

    k2_main<<<BN / 4, 256, K2_SMEM_BYTES>>>(h, ef, adj, W1, b1, W2, b2);
    k3_upd<<<BN / TR, 256>>>(h, U1, b3, U2, b4, gamma, beta, out);
}

// round 15
// speedup vs baseline: 1.0499x; 1.0499x over previous
#include <cuda_runtime.h>
#include <cuda_fp16.h>
#include <cstdint>

#define BN 2048   // B*N rows
#define NN 256    // N (neighbors)
#define D  128
#define E  64

// Scratch (device globals: allocation-free rule)
__device__ __align__(16) float g_aggmean[BN * D];
__device__ __align__(16) float g_aggmax[BN * D];

__device__ __forceinline__ float tanh_fast(float x) {
    float y;
    asm("tanh.approx.f32 %0, %1;" : "=f"(y) : "f"(x));
    return y;
}

__device__ __forceinline__ uint32_t pack_h2(float a, float b) {
    __half2 v = __floats2half2_rn(a, b);   // a = low half (even k)
    uint32_t r;
    memcpy(&r, &v, 4);
    return r;
}

// ---------------------------------------------------------------------------
// K2 (R13 config + vectorized R-build): 4 (b,i) rows per CTA (grid 512).
//  - W2 staged once per CTA as 0.5*W2 fp16-packed transposed (SMEM, pitch 36).
//  - hW1 prologue overlapped with staging (h via __ldg, W1 direct).
//  - R-build reads s_hW1/sW1e via float4 LDS.128 (16 loads vs 64 scalar).
//  - Accumulators init 0.5*b2 -> MMA yields 0.5*logit; tanh-space reduction:
//    S = sum(vm*th), T = max(sgn_d*th); final mean/max recovered per d.
// ---------------------------------------------------------------------------
#define K2_SMEM_BYTES (9032 * 4)

__global__ void __launch_bounds__(256) k2_main(
    const float* __restrict__ h, const float* __restrict__ ef,
    const unsigned char* __restrict__ adj,
    const float* __restrict__ W1, const float* __restrict__ b1,
    const float* __restrict__ W2, const float* __restrict__ b2) {
    extern __shared__ float sm[];
    uint32_t* sW2T  = (uint32_t*)sm;          // [d][epair] packed half2 (0.5*W2), pitch 36
    uint32_t* sRh   = (uint32_t*)(sm + 4608); // [row][epair] packed half2, pitch 36
    float* s_hW1x = sm + 6912;   // [4][64]
    float* sW1e   = sm + 7168;   // [3][64]
    float* s_b2   = sm + 7360;   // [128] = 0.5*b2
    float* s_hx   = sm + 7488;   // [4][128]
    float* s_redS = sm + 8000;   // [2][128]
    float* s_redT = sm + 8256;   // [2][128]
    int*   s_jidx = (int*)(sm + 8768);
    int*   s_misc = s_jidx + 256;

    const int bi0  = blockIdx.x * 4;
    const int tid  = threadIdx.x;
    const int lane = tid & 31;
    const int warp = tid >> 5;
    const int gid  = lane >> 2;   // 0..7
    const int tg   = lane & 3;    // 0..3
    const int wm   = warp & 1;    // M-group (rows)
    const int wn   = warp >> 1;   // N-group (cols)

    if (tid < 128) {
        const int r = tid >> 5, c = tid & 31;
        ((float4*)&s_hx[r * 128])[c] = ((const float4*)(h + (size_t)(bi0 + r) * D))[c];
    }
    // Stage 0.5*W2 transposed+packed
    for (int idx = tid; idx < 32 * D; idx += 256) {
        const int ep = idx >> 7, d = idx & 127;
        const float w0 = 0.5f * W2[(2 * ep) * D + d];
        const float w1 = 0.5f * W2[(2 * ep + 1) * D + d];
        sW2T[d * 36 + ep] = pack_h2(w0, w1);
    }
    for (int idx = tid; idx < 3 * E; idx += 256) sW1e[idx] = W1[D * E + idx];
    if (tid < D) s_b2[tid] = 0.5f * b2[tid];

    // hW1 prologue (h via __ldg: overlaps staging loads)
    {
        const int r = tid >> 6;
        const int e = tid & 63;
        const float* hr = h + (size_t)(bi0 + r) * D;
        float a0 = 0.f, a1 = 0.f;
#pragma unroll 8
        for (int k = 0; k < 128; k += 2) {
            a0 = fmaf(__ldg(hr + k),     W1[k * E + e],       a0);
            a1 = fmaf(__ldg(hr + k + 1), W1[(k + 1) * E + e], a1);
        }
        s_hW1x[r * 64 + e] = a0 + a1 + b1[e];
    }

    for (int sub = 0; sub < 4; sub++) {
        const int bi = bi0 + sub;
        __syncthreads();   // staging + prologue complete (sub 0); buffer reuse (sub>0)

        const float* s_hW1 = s_hW1x + sub * 64;
        const float* s_h   = s_hx + sub * 128;

        const bool m = adj[(size_t)bi * NN + tid] != 0;
        const unsigned bal = __ballot_sync(0xffffffffu, m);
        if (lane == 0) s_misc[warp] = __popc(bal);
        __syncthreads();
        int base = 0, cnt = 0;
#pragma unroll
        for (int w = 0; w < 8; w++) {
            const int c = s_misc[w];
            if (w < warp) base += c;
            cnt += c;
        }
        if (m) s_jidx[base + __popc(bal & ((1u << lane) - 1u))] = tid;
        __syncthreads();

        // Per-sub per-thread constants: half-bias + sign for the 8 d's
        float bh[8], sgn[8];
#pragma unroll
        for (int nt = 0; nt < 4; nt++)
#pragma unroll
            for (int q = 0; q < 2; q++) {
                const int d = wn * 32 + nt * 8 + 2 * tg + q;
                bh[nt * 2 + q]  = s_b2[d];
                sgn[nt * 2 + q] = (s_h[d] >= 0.f) ? 1.f : -1.f;
            }

        float S[8], T[8];
#pragma unroll
        for (int i = 0; i < 8; i++) { S[i] = 0.f; T[i] = -1e30f; }

        const int nTiles = (cnt + 63) >> 6;
        const int rrow = tid >> 2;
        const int re0  = (tid & 3) << 4;
        const int rp0  = (tid & 3) << 3;

        // Vectorized R-build base pointers (re0 is 16-float aligned)
        const float4* hw4 = (const float4*)(s_hW1 + re0);
        const float4* we0 = (const float4*)(sW1e + re0);
        const float4* we1 = (const float4*)(sW1e + 64 + re0);
        const float4* we2 = (const float4*)(sW1e + 128 + re0);

        for (int t = 0; t < nTiles; t++) {
            if (t) __syncthreads();
            float f0 = 0.f, f1 = 0.f, f2v = 0.f;
            const int jg = t * 64 + rrow;
            if (jg < cnt) {
                const float* p = ef + ((size_t)bi * NN + s_jidx[jg]) * 3;
                f0 = p[0]; f1 = p[1]; f2v = p[2];
            }
            // ---- Build R tile (64 rows x 64 e): float4 LDS + fmaf chains ----
#pragma unroll
            for (int i4 = 0; i4 < 4; i4++) {
                const float4 hv = hw4[i4];
                const float4 a  = we0[i4];
                const float4 b  = we1[i4];
                const float4 cc = we2[i4];
                const float p0 = fmaxf(hv.x + f0 * a.x + f1 * b.x + f2v * cc.x, 0.f);
                const float p1 = fmaxf(hv.y + f0 * a.y + f1 * b.y + f2v * cc.y, 0.f);
                const float p2 = fmaxf(hv.z + f0 * a.z + f1 * b.z + f2v * cc.z, 0.f);
                const float p3 = fmaxf(hv.w + f0 * a.w + f1 * b.w + f2v * cc.w, 0.f);
                sRh[rrow * 36 + rp0 + i4 * 2]     = pack_h2(p0, p1);
                sRh[rrow * 36 + rp0 + i4 * 2 + 1] = pack_h2(p2, p3);
            }
            __syncthreads();

            // ---- 64x128 half-logits: init accum with 0.5*b2 ----
            float c[2][4][4];
#pragma unroll
            for (int mt = 0; mt < 2; mt++)
#pragma unroll
                for (int nt = 0; nt < 4; nt++)
#pragma unroll
                    for (int q = 0; q < 4; q++) c[mt][nt][q] = bh[nt * 2 + (q & 1)];

#pragma unroll
            for (int kc = 0; kc < 4; kc++) {
                const int kp = kc * 8;
                uint32_t a[2][4], b[4][2];
#pragma unroll
                for (int mt = 0; mt < 2; mt++) {
                    const int row = wm * 32 + mt * 16 + gid;
                    const uint32_t* pr = sRh + row * 36 + kp + tg;
                    a[mt][0] = pr[0];
                    a[mt][1] = pr[8 * 36];
                    a[mt][2] = pr[4];
                    a[mt][3] = pr[8 * 36 + 4];
                }
#pragma unroll
                for (int nt = 0; nt < 4; nt++) {
                    const int col = wn * 32 + nt * 8 + gid;
                    const uint32_t* pb = sW2T + col * 36 + kp + tg;
                    b[nt][0] = pb[0];
                    b[nt][1] = pb[4];
                }
#pragma unroll
                for (int mt = 0; mt < 2; mt++)
#pragma unroll
                    for (int nt = 0; nt < 4; nt++) {
                        asm("mma.sync.aligned.m16n8k16.row.col.f32.f16.f16.f32 "
                            "{%0,%1,%2,%3}, {%4,%5,%6,%7}, {%8,%9}, {%0,%1,%2,%3};\n"
                            : "+f"(c[mt][nt][0]), "+f"(c[mt][nt][1]),
                              "+f"(c[mt][nt][2]), "+f"(c[mt][nt][3])
                            : "r"(a[mt][0]), "r"(a[mt][1]), "r"(a[mt][2]), "r"(a[mt][3]),
                              "r"(b[nt][0]), "r"(b[nt][1]));
                    }
            }

            // ---- Epilogue (tanh space): th = tanh(0.5*logit) ----
#pragma unroll
            for (int mt = 0; mt < 2; mt++)
#pragma unroll
                for (int q = 0; q < 4; q++) {
                    const int rloc = wm * 32 + mt * 16 + gid + ((q >> 1) << 3);
                    const float vm = ((t * 64 + rloc) < cnt) ? 1.f : 0.f;
#pragma unroll
                    for (int nt = 0; nt < 4; nt++) {
                        const int si = nt * 2 + (q & 1);
                        const float th = tanh_fast(c[mt][nt][q]);
                        S[si] = fmaf(vm, th, S[si]);
                        float tt = sgn[si] * th;
                        tt = (vm != 0.f) ? tt : -1e30f;
                        T[si] = fmaxf(T[si], tt);
                    }
                }
        }

        // ---- Reduce across the 8 lanes sharing each d ----
#pragma unroll
        for (int i = 0; i < 8; i++) {
#pragma unroll
            for (int off = 4; off < 32; off <<= 1) {
                S[i] += __shfl_xor_sync(0xffffffffu, S[i], off);
                T[i]  = fmaxf(T[i], __shfl_xor_sync(0xffffffffu, T[i], off));
            }
        }
        __syncthreads();
        if (lane < 4) {
#pragma unroll
            for (int nt = 0; nt < 4; nt++)
#pragma unroll
                for (int q = 0; q < 2; q++) {
                    const int d = wn * 32 + nt * 8 + 2 * lane + q;
                    const int si = nt * 2 + q;
                    s_redS[wm * 128 + d] = S[si];
                    s_redT[wm * 128 + d] = T[si];
                }
        }
        __syncthreads();
        if (tid < D) {
            const float St = s_redS[tid] + s_redS[128 + tid];
            const float Tt = fmaxf(s_redT[tid], s_redT[128 + tid]);
            const float hv = s_h[tid];
            const float cntf = (float)cnt;
            const float cl = (cnt > 0) ? cntf : 1.f;
            const float Sg = fmaf(0.5f, St, 0.5f * cntf);   // sum of sigmoids
            g_aggmean[(size_t)bi * D + tid] = Sg * hv / cl;
            float amax = 0.f;
            if (cnt > 0) {
                const float half_sgn = (hv >= 0.f) ? 0.5f : -0.5f;
                const float gstar = fmaf(half_sgn, Tt, 0.5f);
                amax = hv * gstar;
            }
            g_aggmax[(size_t)bi * D + tid] = amax;
        }
    }
}

// ---------------------------------------------------------------------------
// K3 (verbatim 23.4us proven config): upd MLP + residual + LayerNorm.
// TR=8 rows/CTA, 256 threads, grid=256, s_w tiles + reg prefetch + FFMA2.
// ---------------------------------------------------------------------------
#define TR 8
__global__ void __launch_bounds__(256) k3_upd(
    const float* __restrict__ h,
    const float* __restrict__ U1, const float* __restrict__ b3,
    const float* __restrict__ U2, const float* __restrict__ b4,
    const float* __restrict__ gamma, const float* __restrict__ beta,
    float* __restrict__ out) {
    __shared__ __align__(16) float s_inT[384][12];
    __shared__ __align__(16) float s_midT[128][12];
    __shared__ __align__(16) float s_w[32][128];
    __shared__ float s_x[TR][129];
    const int tid = threadIdx.x;
    const int r0 = blockIdx.x * TR;

    {
        const int r = tid >> 5, c = tid & 31;
        const int k = c * 4;
        const float4 va = ((const float4*)(h + (size_t)(r0 + r) * D))[c];
        const float4 vb = ((const float4*)(g_aggmean + (size_t)(r0 + r) * D))[c];
        const float4 vc = ((const float4*)(g_aggmax + (size_t)(r0 + r) * D))[c];
        s_inT[k + 0][r] = va.x; s_inT[k + 1][r] = va.y;
        s_inT[k + 2][r] = va.z; s_inT[k + 3][r] = va.w;
        s_inT[128 + k + 0][r] = vb.x; s_inT[128 + k + 1][r] = vb.y;
        s_inT[128 + k + 2][r] = vb.z; s_inT[128 + k + 3][r] = vb.w;
        s_inT[256 + k + 0][r] = vc.x; s_inT[256 + k + 1][r] = vc.y;
        s_inT[256 + k + 2][r] = vc.z; s_inT[256 + k + 3][r] = vc.w;
    }

    const int e  = tid & 127;
    const int rb = (tid >> 7) * 4;

    int lk[4], lc[4];
#pragma unroll
    for (int i = 0; i < 4; i++) { const int idx = tid + i * 256; lk[i] = idx >> 5; lc[i] = idx & 31; }

    unsigned long long a01 = 0ull, a23 = 0ull;
    float4 pf[4];
#pragma unroll
    for (int i = 0; i < 4; i++) pf[i] = ((const float4*)(U1 + lk[i] * D))[lc[i]];
    __syncthreads();

    for (int kc = 0; kc < 384; kc += 32) {
#pragma unroll
        for (int i = 0; i < 4; i++) *(float4*)&s_w[lk[i]][lc[i] * 4] = pf[i];
        __syncthreads();
        if (kc + 32 < 384) {
#pragma unroll
            for (int i = 0; i < 4; i++)
                pf[i] = ((const float4*)(U1 + (kc + 32 + lk[i]) * D))[lc[i]];
        }
#pragma unroll
        for (int kk = 0; kk < 32; kk++) {
            const float wv = s_w[kk][e];
            const ulonglong2 v = *(const ulonglong2*)&s_inT[kc + kk][rb];
            unsigned long long wp;
            asm("mov.b64 %0, {%1, %1};" : "=l"(wp) : "r"(__float_as_uint(wv)));
            asm("fma.rn.f32x2 %0, %1, %2, %0;" : "+l"(a01) : "l"(v.x), "l"(wp));
            asm("fma.rn.f32x2 %0, %1, %2, %0;" : "+l"(a23) : "l"(v.y), "l"(wp));
        }
        __syncthreads();
    }
    {
        const float bb = b3[e];
        uint32_t l0, h0, l1, h1;
        asm("mov.b64 {%0, %1}, %2;" : "=r"(l0), "=r"(h0) : "l"(a01));
        asm("mov.b64 {%0, %1}, %2;" : "=r"(l1), "=r"(h1) : "l"(a23));
        s_midT[e][rb + 0] = fmaxf(__uint_as_float(l0) + bb, 0.f);
        s_midT[e][rb + 1] = fmaxf(__uint_as_float(h0) + bb, 0.f);
        s_midT[e][rb + 2] = fmaxf(__uint_as_float(l1) + bb, 0.f);
        s_midT[e][rb + 3] = fmaxf(__uint_as_float(h1) + bb, 0.f);
    }
    a01 = 0ull; a23 = 0ull;
#pragma unroll
    for (int i = 0; i < 4; i++) pf[i] = ((const float4*)(U2 + lk[i] * D))[lc[i]];
    __syncthreads();

    for (int kc = 0; kc < 128; kc += 32) {
#pragma unroll
        for (int i = 0; i < 4; i++) *(float4*)&s_w[lk[i]][lc[i] * 4] = pf[i];
        __syncthreads();
        if (kc + 32 < 128) {
#pragma unroll
            for (int i = 0; i < 4; i++)
                pf[i] = ((const float4*)(U2 + (kc + 32 + lk[i]) * D))[lc[i]];
        }
#pragma unroll
        for (int kk = 0; kk < 32; kk++) {
            const float wv = s_w[kk][e];
            const ulonglong2 v = *(const ulonglong2*)&s_midT[kc + kk][rb];
            unsigned long long wp;
            asm("mov.b64 %0, {%1, %1};" : "=l"(wp) : "r"(__float_as_uint(wv)));
            asm("fma.rn.f32x2 %0, %1, %2, %0;" : "+l"(a01) : "l"(v.x), "l"(wp));
            asm("fma.rn.f32x2 %0, %1, %2, %0;" : "+l"(a23) : "l"(v.y), "l"(wp));
        }
        __syncthreads();
    }
    {
        const float b4v = b4[e];
        uint32_t l0, h0, l1, h1;
        asm("mov.b64 {%0, %1}, %2;" : "=r"(l0), "=r"(h0) : "l"(a01));
        asm("mov.b64 {%0, %1}, %2;" : "=r"(l1), "=r"(h1) : "l"(a23));
        s_x[rb + 0][e] = s_inT[e][rb + 0] + __uint_as_float(l0) + b4v;
        s_x[rb + 1][e] = s_inT[e][rb + 1] + __uint_as_float(h0) + b4v;
        s_x[rb + 2][e] = s_inT[e][rb + 2] + __uint_as_float(l1) + b4v;
        s_x[rb + 3][e] = s_inT[e][rb + 3] + __uint_as_float(h1) + b4v;
    }
    __syncthreads();

    const int warp = tid >> 5, lane = tid & 31;
    float s = 0.f, s2 = 0.f, v[4];
#pragma unroll
    for (int i = 0; i < 4; i++) {
        v[i] = s_x[warp][lane + i * 32];
        s += v[i]; s2 += v[i] * v[i];
    }
#pragma unroll
    for (int off = 1; off < 32; off <<= 1) {
        s  += __shfl_xor_sync(0xffffffffu, s, off);
        s2 += __shfl_xor_sync(0xffffffffu, s2, off);
    }
    const float mu  = s * (1.f / 128.f);
    const float var = s2 * (1.f / 128.f) - mu * mu;
    const float inv = rsqrtf(var + 1e-5f);
#pragma unroll
    for (int i = 0; i < 4; i++) {
        const int d = lane + i * 32;
        out[(size_t)(r0 + warp) * D + d] = (v[i] - mu) * inv * gamma[d] + beta[d];
    }
}

// ---------------------------------------------------------------------------
extern "C" void kernel_launch(void* const* d_in, const int* in_sizes, int n_in,
                              void* d_out, int out_size) {
    const float* h    = (const float*)d_in[0];
    const float* ef   = (const float*)d_in[1];
    const unsigned char* adj = (const unsigned char*)d_in[2];
    const float* W1   = (const float*)d_in[3];
    const float* b1   = (const float*)d_in[4];
    const float* W2   = (const float*)d_in[5];
    const float* b2   = (const float*)d_in[6];
    const float* U1   = (const float*)d_in[7];
    const float* b3   = (const float*)d_in[8];
    const float* U2   = (const float*)d_in[9];
    const float* b4   = (const float*)d_in[10];
    const float* gamma= (const float*)d_in[11];
    const float* beta = (const float*)d_in[12];
    float* out = (float*)d_out;

    cudaFuncSetAttribute(k2_main, cudaFuncAttributeMaxDynamicSharedMemorySize,
                         K2_SMEM_BYTES);

    k2_main<<<BN / 4, 256, K2_SMEM_BYTES>>>(h, ef, adj, W1, b1, W2, b2);
    k3_upd<<<BN / TR, 256>>>(h, U1, b3, U2, b4, gamma, beta, out);
}

// round 16
// speedup vs baseline: 1.0787x; 1.0275x over previous
#include <cuda_runtime.h>
#include <cuda_fp16.h>
#include <cstdint>

#define BN 2048   // B*N rows
#define NN 256    // N (neighbors)
#define D  128
#define E  64

// Scratch (device globals: allocation-free rule)
__device__ __align__(16) float g_aggmean[BN * D];
__device__ __align__(16) float g_aggmax[BN * D];

__device__ __forceinline__ float tanh_fast(float x) {
    float y;
    asm("tanh.approx.f32 %0, %1;" : "=f"(y) : "f"(x));
    return y;
}

__device__ __forceinline__ uint32_t pack_h2(float a, float b) {
    __half2 v = __floats2half2_rn(a, b);   // a = low half (even k)
    uint32_t r;
    memcpy(&r, &v, 4);
    return r;
}

// ---------------------------------------------------------------------------
// K2: 4 (b,i) rows per CTA (grid 512).
//  - 32-row j-tiles, double-buffered sRh (two 32x36 buffers in the old
//    64x36 footprint): 1 sync/tile, build(t+1) overlaps MMA(t), ~9% less
//    padding waste vs 64-row tiles.
//  - W2 staged once per CTA as 0.5*W2 fp16-packed transposed (pitch 36).
//  - hW1 prologue overlapped with staging (h via __ldg, W1 direct).
//  - Accumulators init 0.5*b2 -> MMA yields 0.5*logit; tanh-space reduction.
// ---------------------------------------------------------------------------
#define K2_SMEM_BYTES (9032 * 4)

__global__ void __launch_bounds__(256) k2_main(
    const float* __restrict__ h, const float* __restrict__ ef,
    const unsigned char* __restrict__ adj,
    const float* __restrict__ W1, const float* __restrict__ b1,
    const float* __restrict__ W2, const float* __restrict__ b2) {
    extern __shared__ float sm[];
    uint32_t* sW2T  = (uint32_t*)sm;          // [d][epair] packed half2 (0.5*W2), pitch 36
    uint32_t* sRh   = (uint32_t*)(sm + 4608); // 2 buffers of [32][36] packed half2
    float* s_hW1x = sm + 6912;   // [4][64]
    float* sW1e   = sm + 7168;   // [3][64]
    float* s_b2   = sm + 7360;   // [128] = 0.5*b2
    float* s_hx   = sm + 7488;   // [4][128]
    float* s_redS = sm + 8000;   // [2][128]
    float* s_redT = sm + 8256;   // [2][128]
    int*   s_jidx = (int*)(sm + 8768);
    int*   s_misc = s_jidx + 256;

    const int bi0  = blockIdx.x * 4;
    const int tid  = threadIdx.x;
    const int lane = tid & 31;
    const int warp = tid >> 5;
    const int gid  = lane >> 2;   // 0..7
    const int tg   = lane & 3;    // 0..3
    const int wm   = warp & 1;    // row-half (16 rows)
    const int wn   = warp >> 1;   // col group (32 cols)

    if (tid < 128) {
        const int r = tid >> 5, c = tid & 31;
        ((float4*)&s_hx[r * 128])[c] = ((const float4*)(h + (size_t)(bi0 + r) * D))[c];
    }
    // Stage 0.5*W2 transposed+packed
    for (int idx = tid; idx < 32 * D; idx += 256) {
        const int ep = idx >> 7, d = idx & 127;
        const float w0 = 0.5f * W2[(2 * ep) * D + d];
        const float w1 = 0.5f * W2[(2 * ep + 1) * D + d];
        sW2T[d * 36 + ep] = pack_h2(w0, w1);
    }
    for (int idx = tid; idx < 3 * E; idx += 256) sW1e[idx] = W1[D * E + idx];
    if (tid < D) s_b2[tid] = 0.5f * b2[tid];

    // hW1 prologue (h via __ldg: overlaps staging loads)
    {
        const int r = tid >> 6;
        const int e = tid & 63;
        const float* hr = h + (size_t)(bi0 + r) * D;
        float a0 = 0.f, a1 = 0.f;
#pragma unroll 8
        for (int k = 0; k < 128; k += 2) {
            a0 = fmaf(__ldg(hr + k),     W1[k * E + e],       a0);
            a1 = fmaf(__ldg(hr + k + 1), W1[(k + 1) * E + e], a1);
        }
        s_hW1x[r * 64 + e] = a0 + a1 + b1[e];
    }

    for (int sub = 0; sub < 4; sub++) {
        const int bi = bi0 + sub;
        __syncthreads();   // staging + prologue complete (sub 0); buffer reuse (sub>0)

        const float* s_hW1 = s_hW1x + sub * 64;
        const float* s_h   = s_hx + sub * 128;

        const bool m = adj[(size_t)bi * NN + tid] != 0;
        const unsigned bal = __ballot_sync(0xffffffffu, m);
        if (lane == 0) s_misc[warp] = __popc(bal);
        __syncthreads();
        int base = 0, cnt = 0;
#pragma unroll
        for (int w = 0; w < 8; w++) {
            const int c = s_misc[w];
            if (w < warp) base += c;
            cnt += c;
        }
        if (m) s_jidx[base + __popc(bal & ((1u << lane) - 1u))] = tid;
        __syncthreads();

        // Per-sub per-thread constants: half-bias + sign for the 8 d's
        float bh[8], sgn[8];
#pragma unroll
        for (int nt = 0; nt < 4; nt++)
#pragma unroll
            for (int q = 0; q < 2; q++) {
                const int d = wn * 32 + nt * 8 + 2 * tg + q;
                bh[nt * 2 + q]  = s_b2[d];
                sgn[nt * 2 + q] = (s_h[d] >= 0.f) ? 1.f : -1.f;
            }

        float S[8], T[8];
#pragma unroll
        for (int i = 0; i < 8; i++) { S[i] = 0.f; T[i] = -1e30f; }

        const int nTiles = (cnt + 31) >> 5;
        const int rrow = tid >> 3;          // 0..31 (build row)
        const int re0  = (tid & 7) << 3;    // e base (8 per thread)
        const int rp0  = (tid & 7) << 2;    // e-pair base

        // Vectorized R-build base pointers (re0 is 8-float = 32B aligned)
        const float4* hw4 = (const float4*)(s_hW1 + re0);
        const float4* we0 = (const float4*)(sW1e + re0);
        const float4* we1 = (const float4*)(sW1e + 64 + re0);
        const float4* we2 = (const float4*)(sW1e + 128 + re0);

        auto build_tile = [&](int t, uint32_t* buf) {
            float f0 = 0.f, f1 = 0.f, f2v = 0.f;
            const int jg = t * 32 + rrow;
            if (jg < cnt) {
                const float* p = ef + ((size_t)bi * NN + s_jidx[jg]) * 3;
                f0 = p[0]; f1 = p[1]; f2v = p[2];
            }
#pragma unroll
            for (int i4 = 0; i4 < 2; i4++) {
                const float4 hv = hw4[i4];
                const float4 a  = we0[i4];
                const float4 b  = we1[i4];
                const float4 cc = we2[i4];
                const float p0 = fmaxf(hv.x + f0 * a.x + f1 * b.x + f2v * cc.x, 0.f);
                const float p1 = fmaxf(hv.y + f0 * a.y + f1 * b.y + f2v * cc.y, 0.f);
                const float p2 = fmaxf(hv.z + f0 * a.z + f1 * b.z + f2v * cc.z, 0.f);
                const float p3 = fmaxf(hv.w + f0 * a.w + f1 * b.w + f2v * cc.w, 0.f);
                buf[rrow * 36 + rp0 + i4 * 2]     = pack_h2(p0, p1);
                buf[rrow * 36 + rp0 + i4 * 2 + 1] = pack_h2(p2, p3);
            }
        };

        build_tile(0, sRh);   // tile 0 into buffer 0

        for (int t = 0; t < nTiles; t++) {
            __syncthreads();  // buf[t&1] built; previous tile's MMA reads done
            if (t + 1 < nTiles) build_tile(t + 1, sRh + ((t + 1) & 1) * 1152);

            const uint32_t* bufc = sRh + (t & 1) * 1152;

            // ---- 32x128 half-logits: warp = 16 rows x 32 cols, K=64 ----
            float c[4][4];
#pragma unroll
            for (int nt = 0; nt < 4; nt++)
#pragma unroll
                for (int q = 0; q < 4; q++) c[nt][q] = bh[nt * 2 + (q & 1)];

#pragma unroll
            for (int kc = 0; kc < 4; kc++) {
                const int kp = kc * 8;
                uint32_t a[4], b[4][2];
                {
                    const int row = wm * 16 + gid;
                    const uint32_t* pr = bufc + row * 36 + kp + tg;
                    a[0] = pr[0];
                    a[1] = pr[8 * 36];
                    a[2] = pr[4];
                    a[3] = pr[8 * 36 + 4];
                }
#pragma unroll
                for (int nt = 0; nt < 4; nt++) {
                    const int col = wn * 32 + nt * 8 + gid;
                    const uint32_t* pb = sW2T + col * 36 + kp + tg;
                    b[nt][0] = pb[0];
                    b[nt][1] = pb[4];
                }
#pragma unroll
                for (int nt = 0; nt < 4; nt++) {
                    asm("mma.sync.aligned.m16n8k16.row.col.f32.f16.f16.f32 "
                        "{%0,%1,%2,%3}, {%4,%5,%6,%7}, {%8,%9}, {%0,%1,%2,%3};\n"
                        : "+f"(c[nt][0]), "+f"(c[nt][1]),
                          "+f"(c[nt][2]), "+f"(c[nt][3])
                        : "r"(a[0]), "r"(a[1]), "r"(a[2]), "r"(a[3]),
                          "r"(b[nt][0]), "r"(b[nt][1]));
                }
            }

            // ---- Epilogue (tanh space): th = tanh(0.5*logit) ----
#pragma unroll
            for (int q = 0; q < 4; q++) {
                const int rloc = wm * 16 + gid + ((q >> 1) << 3);
                const float vm = ((t * 32 + rloc) < cnt) ? 1.f : 0.f;
#pragma unroll
                for (int nt = 0; nt < 4; nt++) {
                    const int si = nt * 2 + (q & 1);
                    const float th = tanh_fast(c[nt][q]);
                    S[si] = fmaf(vm, th, S[si]);
                    float tt = sgn[si] * th;
                    tt = (vm != 0.f) ? tt : -1e30f;
                    T[si] = fmaxf(T[si], tt);
                }
            }
        }

        // ---- Reduce across the 8 lanes sharing each d ----
#pragma unroll
        for (int i = 0; i < 8; i++) {
#pragma unroll
            for (int off = 4; off < 32; off <<= 1) {
                S[i] += __shfl_xor_sync(0xffffffffu, S[i], off);
                T[i]  = fmaxf(T[i], __shfl_xor_sync(0xffffffffu, T[i], off));
            }
        }
        __syncthreads();
        if (lane < 4) {
#pragma unroll
            for (int nt = 0; nt < 4; nt++)
#pragma unroll
                for (int q = 0; q < 2; q++) {
                    const int d = wn * 32 + nt * 8 + 2 * lane + q;
                    const int si = nt * 2 + q;
                    s_redS[wm * 128 + d] = S[si];
                    s_redT[wm * 128 + d] = T[si];
                }
        }
        __syncthreads();
        if (tid < D) {
            const float St = s_redS[tid] + s_redS[128 + tid];
            const float Tt = fmaxf(s_redT[tid], s_redT[128 + tid]);
            const float hv = s_h[tid];
            const float cntf = (float)cnt;
            const float cl = (cnt > 0) ? cntf : 1.f;
            const float Sg = fmaf(0.5f, St, 0.5f * cntf);   // sum of sigmoids
            g_aggmean[(size_t)bi * D + tid] = Sg * hv / cl;
            float amax = 0.f;
            if (cnt > 0) {
                const float half_sgn = (hv >= 0.f) ? 0.5f : -0.5f;
                const float gstar = fmaf(half_sgn, Tt, 0.5f);
                amax = hv * gstar;
            }
            g_aggmax[(size_t)bi * D + tid] = amax;
        }
    }
}

// ---------------------------------------------------------------------------
// K3 (verbatim 23.6us proven config): upd MLP + residual + LayerNorm.
// TR=8 rows/CTA, 256 threads, grid=256, s_w tiles + reg prefetch + FFMA2.
// ---------------------------------------------------------------------------
#define TR 8
__global__ void __launch_bounds__(256) k3_upd(
    const float* __restrict__ h,
    const float* __restrict__ U1, const float* __restrict__ b3,
    const float* __restrict__ U2, const float* __restrict__ b4,
    const float* __restrict__ gamma, const float* __restrict__ beta,
    float* __restrict__ out) {
    __shared__ __align__(16) float s_inT[384][12];
    __shared__ __align__(16) float s_midT[128][12];
    __shared__ __align__(16) float s_w[32][128];
    __shared__ float s_x[TR][129];
    const int tid = threadIdx.x;
    const int r0 = blockIdx.x * TR;

    {
        const int r = tid >> 5, c = tid & 31;
        const int k = c * 4;
        const float4 va = ((const float4*)(h + (size_t)(r0 + r) * D))[c];
        const float4 vb = ((const float4*)(g_aggmean + (size_t)(r0 + r) * D))[c];
        const float4 vc = ((const float4*)(g_aggmax + (size_t)(r0 + r) * D))[c];
        s_inT[k + 0][r] = va.x; s_inT[k + 1][r] = va.y;
        s_inT[k + 2][r] = va.z; s_inT[k + 3][r] = va.w;
        s_inT[128 + k + 0][r] = vb.x; s_inT[128 + k + 1][r] = vb.y;
        s_inT[128 + k + 2][r] = vb.z; s_inT[128 + k + 3][r] = vb.w;
        s_inT[256 + k + 0][r] = vc.x; s_inT[256 + k + 1][r] = vc.y;
        s_inT[256 + k + 2][r] = vc.z; s_inT[256 + k + 3][r] = vc.w;
    }

    const int e  = tid & 127;
    const int rb = (tid >> 7) * 4;

    int lk[4], lc[4];
#pragma unroll
    for (int i = 0; i < 4; i++) { const int idx = tid + i * 256; lk[i] = idx >> 5; lc[i] = idx & 31; }

    unsigned long long a01 = 0ull, a23 = 0ull;
    float4 pf[4];
#pragma unroll
    for (int i = 0; i < 4; i++) pf[i] = ((const float4*)(U1 + lk[i] * D))[lc[i]];
    __syncthreads();

    for (int kc = 0; kc < 384; kc += 32) {
#pragma unroll
        for (int i = 0; i < 4; i++) *(float4*)&s_w[lk[i]][lc[i] * 4] = pf[i];
        __syncthreads();
        if (kc + 32 < 384) {
#pragma unroll
            for (int i = 0; i < 4; i++)
                pf[i] = ((const float4*)(U1 + (kc + 32 + lk[i]) * D))[lc[i]];
        }
#pragma unroll
        for (int kk = 0; kk < 32; kk++) {
            const float wv = s_w[kk][e];
            const ulonglong2 v = *(const ulonglong2*)&s_inT[kc + kk][rb];
            unsigned long long wp;
            asm("mov.b64 %0, {%1, %1};" : "=l"(wp) : "r"(__float_as_uint(wv)));
            asm("fma.rn.f32x2 %0, %1, %2, %0;" : "+l"(a01) : "l"(v.x), "l"(wp));
            asm("fma.rn.f32x2 %0, %1, %2, %0;" : "+l"(a23) : "l"(v.y), "l"(wp));
        }
        __syncthreads();
    }
    {
        const float bb = b3[e];
        uint32_t l0, h0, l1, h1;
        asm("mov.b64 {%0, %1}, %2;" : "=r"(l0), "=r"(h0) : "l"(a01));
        asm("mov.b64 {%0, %1}, %2;" : "=r"(l1), "=r"(h1) : "l"(a23));
        s_midT[e][rb + 0] = fmaxf(__uint_as_float(l0) + bb, 0.f);
        s_midT[e][rb + 1] = fmaxf(__uint_as_float(h0) + bb, 0.f);
        s_midT[e][rb + 2] = fmaxf(__uint_as_float(l1) + bb, 0.f);
        s_midT[e][rb + 3] = fmaxf(__uint_as_float(h1) + bb, 0.f);
    }
    a01 = 0ull; a23 = 0ull;
#pragma unroll
    for (int i = 0; i < 4; i++) pf[i] = ((const float4*)(U2 + lk[i] * D))[lc[i]];
    __syncthreads();

    for (int kc = 0; kc < 128; kc += 32) {
#pragma unroll
        for (int i = 0; i < 4; i++) *(float4*)&s_w[lk[i]][lc[i] * 4] = pf[i];
        __syncthreads();
        if (kc + 32 < 128) {
#pragma unroll
            for (int i = 0; i < 4; i++)
                pf[i] = ((const float4*)(U2 + (kc + 32 + lk[i]) * D))[lc[i]];
        }
#pragma unroll
        for (int kk = 0; kk < 32; kk++) {
            const float wv = s_w[kk][e];
            const ulonglong2 v = *(const ulonglong2*)&s_midT[kc + kk][rb];
            unsigned long long wp;
            asm("mov.b64 %0, {%1, %1};" : "=l"(wp) : "r"(__float_as_uint(wv)));
            asm("fma.rn.f32x2 %0, %1, %2, %0;" : "+l"(a01) : "l"(v.x), "l"(wp));
            asm("fma.rn.f32x2 %0, %1, %2, %0;" : "+l"(a23) : "l"(v.y), "l"(wp));
        }
        __syncthreads();
    }
    {
        const float b4v = b4[e];
        uint32_t l0, h0, l1, h1;
        asm("mov.b64 {%0, %1}, %2;" : "=r"(l0), "=r"(h0) : "l"(a01));
        asm("mov.b64 {%0, %1}, %2;" : "=r"(l1), "=r"(h1) : "l"(a23));
        s_x[rb + 0][e] = s_inT[e][rb + 0] + __uint_as_float(l0) + b4v;
        s_x[rb + 1][e] = s_inT[e][rb + 1] + __uint_as_float(h0) + b4v;
        s_x[rb + 2][e] = s_inT[e][rb + 2] + __uint_as_float(l1) + b4v;
        s_x[rb + 3][e] = s_inT[e][rb + 3] + __uint_as_float(h1) + b4v;
    }
    __syncthreads();

    const int warp = tid >> 5, lane = tid & 31;
    float s = 0.f, s2 = 0.f, v[4];
#pragma unroll
    for (int i = 0; i < 4; i++) {
        v[i] = s_x[warp][lane + i * 32];
        s += v[i]; s2 += v[i] * v[i];
    }
#pragma unroll
    for (int off = 1; off < 32; off <<= 1) {
        s  += __shfl_xor_sync(0xffffffffu, s, off);
        s2 += __shfl_xor_sync(0xffffffffu, s2, off);
    }
    const float mu  = s * (1.f / 128.f);
    const float var = s2 * (1.f / 128.f) - mu * mu;
    const float inv = rsqrtf(var + 1e-5f);
#pragma unroll
    for (int i = 0; i < 4; i++) {
        const int d = lane + i * 32;
        out[(size_t)(r0 + warp) * D + d] = (v[i] - mu) * inv * gamma[d] + beta[d];
    }
}

// ---------------------------------------------------------------------------
extern "C" void kernel_launch(void* const* d_in, const int* in_sizes, int n_in,
                              void* d_out, int out_size) {
    const float* h    = (const float*)d_in[0];
    const float* ef   = (const float*)d_in[1];
    const unsigned char* adj = (const unsigned char*)d_in[2];
    const float* W1   = (const float*)d_in[3];
    const float* b1   = (const float*)d_in[4];
    const float* W2   = (const float*)d_in[5];
    const float* b2   = (const float*)d_in[6];
    const float* U1   = (const float*)d_in[7];
    const float* b3   = (const float*)d_in[8];
    const float* U2   = (const float*)d_in[9];
    const float* b4   = (const float*)d_in[10];
    const float* gamma= (const float*)d_in[11];
    const float* beta = (const float*)d_in[12];
    float* out = (float*)d_out;

    cudaFuncSetAttribute(k2_main, cudaFuncAttributeMaxDynamicSharedMemorySize,
                         K2_SMEM_BYTES);

    k2_main<<<BN / 4, 256, K2_SMEM_BYTES>>>(h, ef, adj, W1, b1, W2, b2);
    k3_upd<<<BN / TR, 256>>>(h, U1, b3, U2, b4, gamma, beta, out);
}